// round 7
// baseline (speedup 1.0000x reference)
#include <cuda_runtime.h>

#define T_LEN   2048
#define CSTEP   16                      // timesteps per chunk
#define NCHUNK  (T_LEN / CSTEP)         // 128
#define NITER   (NCHUNK + 3)            // 4-deep pipeline: L -> A -> B -> C
#define NGRP_C  (CSTEP / 4)             // float4-groups per chunk (4)

__device__ __forceinline__ float tanh_fast(float x) {
    float y;
    asm("tanh.approx.f32 %0, %1;" : "=f"(y) : "f"(x));
    return y;
}

// State in the x10 domain (WU = 10*wu etc); clips at +-1e5 are exact no-ops
// on reachable values (|state| <= O(T) ~ 2e3).
//
// 4-warp pipeline, one chunk skew per stage, one __syncthreads per iteration:
//   warp3 (L): STS chunk k (regs loaded 2 iters ago), LDG chunk k+2
//   warp0 (A): WU chain, chunk k-1 -> REM, D1, ct2 = p - c2*(wu/W)^2
//   warp1 (B): WL chain, chunk k-2 -> X, D2
//   warp2 (C): WD chain + q, chunk k-3 -> global stores
// Every compute stage batch-loads its whole chunk from smem into registers
// first (one exposed LDS latency per chunk), then runs a pure-register,
// fully-unrolled 24-cycle/step carried chain.
__global__ void __launch_bounds__(128, 1) xaj_kernel(
    const float* __restrict__ inputs,
    const float* __restrict__ pwum, const float* __restrict__ pwlm,
    const float* __restrict__ pwdm, const float* __restrict__ pc,
    const float* __restrict__ pb,  const float* __restrict__ pk1,
    const float* __restrict__ pk2, const float* __restrict__ pk3,
    float* __restrict__ out, int B)
{
    __shared__ float sPET[2][CSTEP][32];
    __shared__ float sP  [2][CSTEP][32];
    __shared__ float sREM[2][CSTEP][32];
    __shared__ float sD1 [2][CSTEP][32];
    __shared__ float sX  [2][CSTEP][32];
    __shared__ float sD2 [2][CSTEP][32];
    __shared__ float sCT [3][CSTEP][32];   // ct2: A -> C (distance 2)

    const int lane = threadIdx.x & 31;
    const int wid  = threadIdx.x >> 5;
    const int row  = blockIdx.x * 32 + lane;

    // scalar params (reference arg swap: runoff_production(wu, wd, wl, p,
    // wum, wdm, wlm, b, c))
    const float wum_p = pwum[0] * 19.9f + 0.1f;
    const float wlm_p = pwdm[0] * 30.0f + 60.0f;
    const float wdm_p = pwlm[0] * 60.0f + 60.0f;
    const float W      = wum_p + wlm_p + wdm_p;
    const float invW10 = 0.1f / W;
    const float negc2  = -(pc[0] * 0.19f + 0.01f);
    const float negb2  = -(pb[0] * 0.30f + 0.10f);
    const float k1 = pk1[0] * 0.69f + 0.01f;
    const float k2 = pk2[0] * 0.69f + 0.01f;
    const float k3 = pk3[0] * 0.89f + 0.01f;
    const float F  = k1 + 0.5f * k2 * (1.0f - k1)
                   + 0.25f * k3 * (1.0f - k2) * (1.0f - k1);
    const float halfF = 0.5f * F;

    const float4* __restrict__ in4 =
        reinterpret_cast<const float4*>(inputs + (size_t)row * (T_LEN * 3));
    float4* __restrict__ out4 =
        reinterpret_cast<float4*>(out + (size_t)row * T_LEN);

    float WU = 0.0f, WL = 0.0f, WD = 0.0f;

    // loader double prefetch buffers: fA holds even chunks, fB odd chunks
    float4 fA[NGRP_C][3], fB[NGRP_C][3];
    if (wid == 3) {
        #pragma unroll
        for (int j = 0; j < NGRP_C; ++j) {
            fA[j][0] = in4[j * 3 + 0];
            fA[j][1] = in4[j * 3 + 1];
            fA[j][2] = in4[j * 3 + 2];
        }
        #pragma unroll
        for (int j = 0; j < NGRP_C; ++j) {
            const int g = NGRP_C + j;
            fB[j][0] = in4[g * 3 + 0];
            fB[j][1] = in4[g * 3 + 1];
            fB[j][2] = in4[g * 3 + 2];
        }
    }

    for (int k = 0; k < NITER; ++k) {
        if (wid == 3) {
            // ---- loader: STS chunk k from regs, LDG chunk k+2 ----
            if (k < NCHUNK) {
                const int slot = k & 1;
                float4 (*f)[3] = (k & 1) ? fB : fA;
                #pragma unroll
                for (int j = 0; j < NGRP_C; ++j) {
                    // (B,T,3): pet = ch0, p = ch2
                    const float pet_[4] = { f[j][0].x, f[j][0].w,
                                            f[j][1].z, f[j][2].y };
                    const float pr_ [4] = { f[j][0].z, f[j][1].y,
                                            f[j][2].x, f[j][2].w };
                    #pragma unroll
                    for (int i = 0; i < 4; ++i) {
                        sPET[slot][j * 4 + i][lane] = 10.0f * pet_[i];
                        sP  [slot][j * 4 + i][lane] = 10.0f * pr_[i];
                    }
                }
                if (k + 2 < NCHUNK) {
                    #pragma unroll
                    for (int j = 0; j < NGRP_C; ++j) {
                        const int g = (k + 2) * NGRP_C + j;
                        f[j][0] = in4[g * 3 + 0];
                        f[j][1] = in4[g * 3 + 1];
                        f[j][2] = in4[g * 3 + 2];
                    }
                }
            }
        } else if (wid == 0) {
            // ---- stage A: WU chain, chunk k-1 ----
            if (k >= 1 && k <= NCHUNK) {
                const int ka = k - 1, slot = ka & 1, cslot = ka % 3;
                float rPET[CSTEP], rP[CSTEP];
                #pragma unroll
                for (int t = 0; t < CSTEP; ++t) {
                    rPET[t] = sPET[slot][t][lane];
                    rP[t]   = sP  [slot][t][lane];
                }
                #pragma unroll
                for (int t = 0; t < CSTEP; ++t) {
                    const float pet10 = rPET[t];
                    const float p10   = rP[t];
                    const float a    = WU - pet10;
                    const float ha   = 0.5f * a;
                    const float ct   = fmaf(-0.5f, pet10, p10);
                    const float base = fmaf(0.5f, WU, ct);
                    const float sum  = WU + p10;
                    const float t1   = tanh_fast(a);
                    const float WUn  = fmaf(t1, ha, base);   // carried: 24cyc
                    const float ET1  = sum - WUn;            // off-chain
                    const float Z    = pet10 - ET1;
                    const float tr   = tanh_fast(Z);
                    const float hZ   = 0.5f * Z;
                    const float REM  = fmaf(tr, hZ, hZ);
                    const float D1   = p10 - ET1;
                    const float u    = WUn * invW10;
                    const float cu   = negc2 * u;
                    const float praw = 0.1f * p10;
                    const float ct2  = fmaf(cu, u, praw);    // p - c2*u^2
                    sREM[slot][t][lane]  = REM;
                    sD1 [slot][t][lane]  = D1;
                    sCT [cslot][t][lane] = ct2;
                    WU = WUn;
                }
            }
        } else if (wid == 1) {
            // ---- stage B: WL chain, chunk k-2 ----
            if (k >= 2 && k <= NCHUNK + 1) {
                const int kb = k - 2, slot = kb & 1;
                float rREM[CSTEP], rD1[CSTEP];
                #pragma unroll
                for (int t = 0; t < CSTEP; ++t) {
                    rREM[t] = sREM[slot][t][lane];
                    rD1[t]  = sD1 [slot][t][lane];
                }
                #pragma unroll
                for (int t = 0; t < CSTEP; ++t) {
                    const float REM = rREM[t];
                    const float D1  = rD1[t];
                    const float t3  = tanh_fast(REM);            // off-chain
                    const float g3  = fmaf(t3, 0.5f, 0.5f);      // H(rem)
                    // carried chain (24cyc): aB -> t2 -> WLn
                    const float aB   = REM - WL;
                    const float t2   = tanh_fast(aB);
                    const float haB  = 0.5f * aB;
                    const float gh   = g3 * haB;
                    const float mB   = fmaf(0.5f, WL, 0.5f * REM);
                    const float g3mB = g3 * mB;
                    const float WLD  = WL + D1;
                    const float rest = WLD - g3mB;
                    WL = fmaf(t2, gh, rest);                     // WL + D1 - ET2
                    // X = REM - ET2, D2 = D1 - ET2, ET2 = g3mB - t2*gh
                    sX [slot][t][lane] = fmaf(t2, gh, REM - g3mB);
                    sD2[slot][t][lane] = fmaf(t2, gh, D1  - g3mB);
                }
            }
        } else {
            // ---- stage C: WD chain + runoff/q, chunk k-3 ----
            if (k >= 3) {
                const int kc = k - 3, slot = kc & 1, cslot = kc % 3;
                float rX[CSTEP], rD2[CSTEP], rCT[CSTEP], qv[CSTEP];
                #pragma unroll
                for (int t = 0; t < CSTEP; ++t) {
                    rX[t]  = sX [slot][t][lane];
                    rD2[t] = sD2[slot][t][lane];
                    rCT[t] = sCT[cslot][t][lane];
                }
                #pragma unroll
                for (int t = 0; t < CSTEP; ++t) {
                    const float X   = rX[t];
                    const float D2  = rD2[t];
                    const float t5  = tanh_fast(X);              // off-chain
                    const float g5  = fmaf(t5, 0.5f, 0.5f);      // H(x)
                    // carried chain (24cyc): aC -> t4 -> WDn
                    const float aC   = X - WD;
                    const float t4   = tanh_fast(aC);
                    const float haC  = 0.5f * aC;
                    const float gh5  = g5 * haC;
                    const float mC   = fmaf(0.5f, WD, 0.5f * X);
                    const float g5mC = g5 * mC;
                    const float WDD  = WD + D2;
                    const float WDn  = fmaf(t4, gh5, WDD - g5mC);
                    // q (off-chain, pipelines across steps)
                    const float v    = WDn * invW10;
                    const float bv   = negb2 * v;
                    const float dd   = fmaf(bv, v, rCT[t]);      // p - s
                    const float tq   = tanh_fast(10.0f * dd);
                    const float qh   = halfF * dd;
                    qv[t] = fmaf(tq, qh, qh);                    // F*H(p-s)*(p-s)
                    WD = WDn;
                }
                #pragma unroll
                for (int j = 0; j < NGRP_C; ++j)
                    out4[kc * NGRP_C + j] = make_float4(
                        qv[j * 4 + 0], qv[j * 4 + 1],
                        qv[j * 4 + 2], qv[j * 4 + 3]);
            }
        }
        __syncthreads();
    }
}

extern "C" void kernel_launch(void* const* d_in, const int* in_sizes, int n_in,
                              void* d_out, int out_size) {
    const float* inputs = (const float*)d_in[0];
    const float* wum = (const float*)d_in[1];
    const float* wlm = (const float*)d_in[2];
    const float* wdm = (const float*)d_in[3];
    const float* c   = (const float*)d_in[4];
    const float* bb  = (const float*)d_in[5];
    const float* k1  = (const float*)d_in[6];
    const float* k2  = (const float*)d_in[7];
    const float* k3  = (const float*)d_in[8];
    float* out = (float*)d_out;

    const int B = in_sizes[0] / (T_LEN * 3);

    dim3 block(128);                // 4 warps: A, B, C, Loader
    dim3 grid(B / 32);              // 32 rows per block
    xaj_kernel<<<grid, block>>>(inputs, wum, wlm, wdm, c, bb, k1, k2, k3, out, B);
}